// round 4
// baseline (speedup 1.0000x reference)
#include <cuda_runtime.h>

// SchNet forward on GB300 — fp32 register-tiled implementation.
// B=8, A=256, N=255 neighbors, NB=NF=128, NG=25, NI=3.

#define Bm   8
#define Am   256
#define Nn   255
#define NBf  128
#define NFf  128
#define NGg  25
#define ROWS (Bm*Am)          // 2048 atoms total
#define EDG  (ROWS*Nn)        // 522240 edges

// Scratch (allocation-free rule: __device__ globals)
__device__ float g_fij[EDG*NGg];   // gaussian-expanded distances, 52.2 MB
__device__ float g_cm [EDG];       // cosine-cutoff * mask per edge
__device__ float g_y  [ROWS*NFf];  // in2f projection
__device__ float g_agg[ROWS*NFf];  // cfconv aggregate

__device__ __forceinline__ float sspf(float x) {
    // softplus(x) - ln2, numerically stable
    return fmaxf(x, 0.f) + log1pf(__expf(-fabsf(x))) - 0.69314718056f;
}

// ---------------------------------------------------------------------------
// x[row, :] = embedding[z[row], :]
__global__ void k_embed(const int* __restrict__ z, const float* __restrict__ emb,
                        float* __restrict__ x) {
    int row = blockIdx.x, t = threadIdx.x;
    x[row*NBf + t] = emb[z[row]*NBf + t];
}

// ---------------------------------------------------------------------------
// Geometry: r_ij, cosine cutoff * mask, gaussian smearing (precomputed once)
__global__ void k_geo(const float* __restrict__ pos, const int* __restrict__ nbr,
                      const float* __restrict__ mask) {
    int row = blockIdx.x, t = threadIdx.x;
    if (t >= Nn) return;
    int b = row >> 8;                       // row / Am
    const float* pa = pos + row*3;
    float ax = pa[0], ay = pa[1], az = pa[2];
    int e = row*Nn + t;
    int j = nbr[e];
    const float* pj = pos + (b*Am + j)*3;
    float dx = pj[0]-ax, dy = pj[1]-ay, dz = pj[2]-az;
    float r = sqrtf(dx*dx + dy*dy + dz*dz + 1e-12f);
    float m = mask[e];
    r *= m;
    float C = (r < 5.0f) ? 0.5f*(cosf(r*0.6283185307179586f) + 1.0f) : 0.f;
    g_cm[e] = C*m;
    const float width = 5.0f/24.0f;
    const float coeff = -0.5f/(width*width);
    float* fp = g_fij + (long long)e*NGg;
    #pragma unroll
    for (int g = 0; g < NGg; g++) {
        float d = r - width*(float)g;
        fp[g] = __expf(coeff*d*d);
    }
}

// ---------------------------------------------------------------------------
// y = x @ in2f   (32 atoms per CTA, 4x4 register tile, K=128)
__global__ void __launch_bounds__(256) k_y(const float* __restrict__ x,
                                           const float* __restrict__ w) {
    extern __shared__ float sm[];
    float* ws = sm;            // 16384
    float* xT = sm + 16384;    // 128*36 (k-major, padded)
    int t = threadIdx.x;
    int row0 = blockIdx.x*32;
    for (int i = t; i < 16384; i += 256) ws[i] = w[i];
    for (int i = t; i < 32*128; i += 256) {
        int m = i >> 7, k = i & 127;
        xT[k*36 + m] = x[(row0+m)*NBf + k];
    }
    __syncthreads();
    int fb = t & 31, nb = t >> 5;
    int f0 = fb*4, m0 = nb*4;
    float acc[4][4] = {};
    #pragma unroll 4
    for (int k = 0; k < 128; k++) {
        float4 xv = *(const float4*)&xT[k*36 + m0];
        float4 wv = *(const float4*)&ws[k*128 + f0];
        float xa[4] = {xv.x, xv.y, xv.z, xv.w};
        float wa[4] = {wv.x, wv.y, wv.z, wv.w};
        #pragma unroll
        for (int mi = 0; mi < 4; mi++)
            #pragma unroll
            for (int fi = 0; fi < 4; fi++) acc[mi][fi] += xa[mi]*wa[fi];
    }
    for (int mi = 0; mi < 4; mi++) {
        float4 o = {acc[mi][0], acc[mi][1], acc[mi][2], acc[mi][3]};
        *(float4*)&g_y[(row0+m0+mi)*NFf + f0] = o;
    }
}

// ---------------------------------------------------------------------------
// Filter network + cfconv aggregation. One CTA per atom, 256 threads.
// Per 32-neighbor tile: H = ssp(f_ij@fw1+b1) -> smem; W' = H@fw2 register tile;
// agg += (W'+b2)*cm*y[nbr].
__global__ void __launch_bounds__(256) k_filter(const int* __restrict__ nbr,
        const float* __restrict__ fw1, const float* __restrict__ fb1,
        const float* __restrict__ fw2, const float* __restrict__ fb2) {
    extern __shared__ float sm[];
    float* fw2s = sm;                 // 16384
    float* fw1s = fw2s + 16384;       // 3200
    float* fb1s = fw1s + 3200;        // 128
    float* fb2s = fb1s + 128;         // 128
    float* Fs   = fb2s + 128;         // 25*32 = 800 (g-major)
    float* Hs   = Fs   + 800;         // 128*36 = 4608 (f-major, padded)
    float* cms  = Hs   + 4608;        // 32
    float* aggS = cms  + 32;          // 128
    int*   nbrs = (int*)(aggS + 128); // 32

    int t = threadIdx.x;
    int row = blockIdx.x;
    int b = row >> 8;

    for (int i = t; i < 16384; i += 256) fw2s[i] = fw2[i];
    for (int i = t; i < 3200;  i += 256) fw1s[i] = fw1[i];
    if (t < 128) { fb1s[t] = fb1[t]; fb2s[t] = fb2[t]; }

    int fb = t & 31, nb = t >> 5;
    int f0 = fb*4, n0 = nb*4;
    float agg4[4] = {};

    for (int tile = 0; tile < 8; tile++) {
        int nbase = tile*32;
        __syncthreads();
        // load gaussian features (transposed to g-major) + cm + neighbor ids
        for (int i = t; i < 800; i += 256) {
            int n = i/25, g = i - n*25;
            int nn = nbase + n;
            Fs[g*32 + n] = (nn < Nn) ? g_fij[(long long)(row*Nn + nn)*NGg + g] : 0.f;
        }
        if (t < 32) {
            int nn = nbase + t;
            cms[t]  = (nn < Nn) ? g_cm[row*Nn + nn] : 0.f;
            nbrs[t] = (nn < Nn) ? nbr [row*Nn + nn] : 0;
        }
        __syncthreads();

        // stage 1: H[n, f] = ssp(sum_g F[n,g]*fw1[g,f] + b1[f])
        float h[4][4];
        #pragma unroll
        for (int ni = 0; ni < 4; ni++)
            #pragma unroll
            for (int fi = 0; fi < 4; fi++) h[ni][fi] = fb1s[f0+fi];
        #pragma unroll
        for (int g = 0; g < NGg; g++) {
            float4 fv = *(const float4*)&Fs[g*32 + n0];
            float4 wv = *(const float4*)&fw1s[g*128 + f0];
            float fa[4] = {fv.x, fv.y, fv.z, fv.w};
            float wa[4] = {wv.x, wv.y, wv.z, wv.w};
            #pragma unroll
            for (int ni = 0; ni < 4; ni++)
                #pragma unroll
                for (int fi = 0; fi < 4; fi++) h[ni][fi] += fa[ni]*wa[fi];
        }
        #pragma unroll
        for (int fi = 0; fi < 4; fi++) {
            float4 o;
            o.x = sspf(h[0][fi]); o.y = sspf(h[1][fi]);
            o.z = sspf(h[2][fi]); o.w = sspf(h[3][fi]);
            *(float4*)&Hs[(f0+fi)*36 + n0] = o;
        }
        __syncthreads();

        // stage 2: W'[n, f] = sum_k H[n,k]*fw2[k,f]
        float acc[4][4] = {};
        #pragma unroll 8
        for (int k = 0; k < 128; k++) {
            float4 hv = *(const float4*)&Hs[k*36 + n0];
            float4 wv = *(const float4*)&fw2s[k*128 + f0];
            float ha[4] = {hv.x, hv.y, hv.z, hv.w};
            float wa[4] = {wv.x, wv.y, wv.z, wv.w};
            #pragma unroll
            for (int ni = 0; ni < 4; ni++)
                #pragma unroll
                for (int fi = 0; fi < 4; fi++) acc[ni][fi] += ha[ni]*wa[fi];
        }

        // epilogue: agg += (W' + b2) * cm * y[nbr]
        #pragma unroll
        for (int ni = 0; ni < 4; ni++) {
            float c = cms[n0+ni];
            int j = nbrs[n0+ni];
            float4 yv = *(const float4*)&g_y[(b*Am + j)*NFf + f0];
            float ya[4] = {yv.x, yv.y, yv.z, yv.w};
            #pragma unroll
            for (int fi = 0; fi < 4; fi++)
                agg4[fi] += (acc[ni][fi] + fb2s[f0+fi]) * c * ya[fi];
        }
    }

    __syncthreads();
    if (t < 128) aggS[t] = 0.f;
    __syncthreads();
    #pragma unroll
    for (int fi = 0; fi < 4; fi++) atomicAdd(&aggS[f0+fi], agg4[fi]);
    __syncthreads();
    if (t < 128) g_agg[row*NFf + t] = aggS[t];
}

// ---------------------------------------------------------------------------
// v = ssp(agg @ f2out_w + b1); x += v @ dense_w + b2   (32 atoms per CTA)
__global__ void __launch_bounds__(256) k_out(const float* __restrict__ w1,
        const float* __restrict__ b1v, const float* __restrict__ w2,
        const float* __restrict__ b2v, float* __restrict__ x) {
    extern __shared__ float sm[];
    float* w1s = sm;             // 16384
    float* w2s = w1s + 16384;    // 16384
    float* aT  = w2s + 16384;    // 4608
    float* vT  = aT  + 4608;     // 4608
    float* b1s = vT  + 4608;     // 128
    float* b2s = b1s + 128;      // 128
    int t = threadIdx.x;
    int row0 = blockIdx.x*32;
    for (int i = t; i < 16384; i += 256) { w1s[i] = w1[i]; w2s[i] = w2[i]; }
    if (t < 128) { b1s[t] = b1v[t]; b2s[t] = b2v[t]; }
    for (int i = t; i < 32*128; i += 256) {
        int m = i >> 7, k = i & 127;
        aT[k*36 + m] = g_agg[(row0+m)*NFf + k];
    }
    __syncthreads();
    int fb = t & 31, nb = t >> 5;
    int d0 = fb*4, m0 = nb*4;

    float acc[4][4] = {};
    #pragma unroll 4
    for (int k = 0; k < 128; k++) {
        float4 av = *(const float4*)&aT[k*36 + m0];
        float4 wv = *(const float4*)&w1s[k*128 + d0];
        float aa[4] = {av.x, av.y, av.z, av.w};
        float wa[4] = {wv.x, wv.y, wv.z, wv.w};
        #pragma unroll
        for (int mi = 0; mi < 4; mi++)
            #pragma unroll
            for (int di = 0; di < 4; di++) acc[mi][di] += aa[mi]*wa[di];
    }
    #pragma unroll
    for (int mi = 0; mi < 4; mi++)
        #pragma unroll
        for (int di = 0; di < 4; di++)
            vT[(d0+di)*36 + (m0+mi)] = sspf(acc[mi][di] + b1s[d0+di]);
    __syncthreads();

    float acc2[4][4] = {};
    #pragma unroll 4
    for (int k = 0; k < 128; k++) {
        float4 av = *(const float4*)&vT[k*36 + m0];
        float4 wv = *(const float4*)&w2s[k*128 + d0];
        float aa[4] = {av.x, av.y, av.z, av.w};
        float wa[4] = {wv.x, wv.y, wv.z, wv.w};
        #pragma unroll
        for (int mi = 0; mi < 4; mi++)
            #pragma unroll
            for (int di = 0; di < 4; di++) acc2[mi][di] += aa[mi]*wa[di];
    }
    #pragma unroll
    for (int mi = 0; mi < 4; mi++) {
        float4 xv = *(float4*)&x[(row0+m0+mi)*NBf + d0];
        xv.x += acc2[mi][0] + b2s[d0+0];
        xv.y += acc2[mi][1] + b2s[d0+1];
        xv.z += acc2[mi][2] + b2s[d0+2];
        xv.w += acc2[mi][3] + b2s[d0+3];
        *(float4*)&x[(row0+m0+mi)*NBf + d0] = xv;
    }
}

// ---------------------------------------------------------------------------
extern "C" void kernel_launch(void* const* d_in, const int* in_sizes, int n_in,
                              void* d_out, int out_size) {
    const int*   z    = (const int*)  d_in[0];
    const float* pos  = (const float*)d_in[1];
    const int*   nbr  = (const int*)  d_in[2];
    const float* mask = (const float*)d_in[3];
    const float* emb  = (const float*)d_in[4];
    const float* fw1  = (const float*)d_in[5];
    const float* fb1  = (const float*)d_in[6];
    const float* fw2  = (const float*)d_in[7];
    const float* fb2  = (const float*)d_in[8];
    const float* in2f = (const float*)d_in[9];
    const float* f2w  = (const float*)d_in[10];
    const float* f2b  = (const float*)d_in[11];
    const float* dw   = (const float*)d_in[12];
    const float* db   = (const float*)d_in[13];
    float* x = (float*)d_out;

    const int YSM = (16384 + 4608) * 4;
    const int FSM = (16384 + 3200 + 128 + 128 + 800 + 4608 + 32 + 128 + 32) * 4;
    const int OSM = (16384*2 + 4608*2 + 128*2) * 4;
    cudaFuncSetAttribute(k_y,      cudaFuncAttributeMaxDynamicSharedMemorySize, YSM);
    cudaFuncSetAttribute(k_filter, cudaFuncAttributeMaxDynamicSharedMemorySize, FSM);
    cudaFuncSetAttribute(k_out,    cudaFuncAttributeMaxDynamicSharedMemorySize, OSM);

    k_embed<<<ROWS, 128>>>(z, emb, x);
    k_geo  <<<ROWS, 256>>>(pos, nbr, mask);
    for (int i = 0; i < 3; i++) {
        k_y     <<<ROWS/32, 256, YSM>>>(x, in2f + i*NBf*NFf);
        k_filter<<<ROWS,    256, FSM>>>(nbr, fw1 + i*NGg*NFf, fb1 + i*NFf,
                                        fw2 + i*NFf*NFf, fb2 + i*NFf);
        k_out   <<<ROWS/32, 256, OSM>>>(f2w + i*NFf*NBf, f2b + i*NBf,
                                        dw + i*NBf*NBf, db + i*NBf, x);
    }
}

// round 5
// speedup vs baseline: 1.6876x; 1.6876x over previous
#include <cuda_runtime.h>

// SchNet forward on GB300 — fp32, LDS-optimized mapping (R5).
// B=8, A=256, N=255 neighbors, NB=NF=128, NG=25, NI=3.

#define Bm   8
#define Am   256
#define Nn   255
#define NBf  128
#define NFf  128
#define NGg  25
#define ROWS (Bm*Am)          // 2048 atoms total

// Scratch (allocation-free rule: __device__ globals; zero-initialized at load)
__device__ float g_fij[ROWS*NGg*256];  // g-major: [row][g][n(256)], 52.4 MB
__device__ float g_cm [ROWS*256];      // cutoff*mask, padded to 256 (slot 255 = 0)
__device__ float g_y  [ROWS*NFf];      // in2f projection
__device__ float g_agg[ROWS*NFf];      // cfconv aggregate

__device__ __forceinline__ float sspf(float x) {
    return fmaxf(x, 0.f) + log1pf(__expf(-fabsf(x))) - 0.69314718056f;
}

// ---------------------------------------------------------------------------
__global__ void k_embed(const int* __restrict__ z, const float* __restrict__ emb,
                        float* __restrict__ x) {
    int row = blockIdx.x, t = threadIdx.x;
    x[row*NBf + t] = emb[z[row]*NBf + t];
}

// ---------------------------------------------------------------------------
// Geometry: writes g_fij in [row][g][n] layout (coalesced across warp per g).
__global__ void k_geo(const float* __restrict__ pos, const int* __restrict__ nbr,
                      const float* __restrict__ mask) {
    int row = blockIdx.x, t = threadIdx.x;
    if (t >= Nn) return;
    int b = row >> 8;
    const float* pa = pos + row*3;
    float ax = pa[0], ay = pa[1], az = pa[2];
    int e = row*Nn + t;
    int j = nbr[e];
    const float* pj = pos + (b*Am + j)*3;
    float dx = pj[0]-ax, dy = pj[1]-ay, dz = pj[2]-az;
    float r = sqrtf(dx*dx + dy*dy + dz*dz + 1e-12f);
    float m = mask[e];
    r *= m;
    float C = (r < 5.0f) ? 0.5f*(cosf(r*0.6283185307179586f) + 1.0f) : 0.f;
    g_cm[row*256 + t] = C*m;
    const float width = 5.0f/24.0f;
    const float coeff = -0.5f/(width*width);
    float* fp = g_fij + (long long)row*NGg*256 + t;
    #pragma unroll
    for (int g = 0; g < NGg; g++) {
        float d = r - width*(float)g;
        fp[g*256] = __expf(coeff*d*d);
    }
}

// ---------------------------------------------------------------------------
// y = x @ in2f   (32 atoms per CTA, 4x4 register tile, K=128)
__global__ void __launch_bounds__(256) k_y(const float* __restrict__ x,
                                           const float* __restrict__ w) {
    extern __shared__ float sm[];
    float* ws = sm;            // 16384
    float* xT = sm + 16384;    // 128*36
    int t = threadIdx.x;
    int row0 = blockIdx.x*32;
    for (int i = t; i < 16384; i += 256) ws[i] = w[i];
    for (int i = t; i < 32*128; i += 256) {
        int m = i >> 7, k = i & 127;
        xT[k*36 + m] = x[(row0+m)*NBf + k];
    }
    __syncthreads();
    int fb = t & 31, nb = t >> 5;
    int f0 = fb*4, m0 = nb*4;
    float acc[4][4] = {};
    #pragma unroll 4
    for (int k = 0; k < 128; k++) {
        float4 xv = *(const float4*)&xT[k*36 + m0];
        float4 wv = *(const float4*)&ws[k*128 + f0];
        float xa[4] = {xv.x, xv.y, xv.z, xv.w};
        float wa[4] = {wv.x, wv.y, wv.z, wv.w};
        #pragma unroll
        for (int mi = 0; mi < 4; mi++)
            #pragma unroll
            for (int fi = 0; fi < 4; fi++) acc[mi][fi] += xa[mi]*wa[fi];
    }
    for (int mi = 0; mi < 4; mi++) {
        float4 o = {acc[mi][0], acc[mi][1], acc[mi][2], acc[mi][3]};
        *(float4*)&g_y[(row0+m0+mi)*NFf + f0] = o;
    }
}

// ---------------------------------------------------------------------------
// Filter network + cfconv aggregation. One CTA per atom, 256 threads.
// Warp w owns f-block w*16..w*16+15. Per warp per k: 2 LDS wavefronts / 512 FMA.
__global__ void __launch_bounds__(256) k_filter(const int* __restrict__ nbr,
        const float* __restrict__ fw1, const float* __restrict__ fb1,
        const float* __restrict__ fw2, const float* __restrict__ fb2) {
    extern __shared__ float sm[];
    float* fw2s = sm;                 // 16384
    float* fw1s = fw2s + 16384;       // 3200
    float* fb1s = fw1s + 3200;        // 128
    float* fb2s = fb1s + 128;         // 128
    float* Fs   = fb2s + 128;         // 25*36 = 900 (g-major, conflict-free fill)
    float* Hs   = Fs   + 900;         // 128*36 = 4608 (k-major, padded)
    float* cms  = Hs   + 4608;        // 32
    float* aggS = cms  + 32;          // 128
    int*   nbrs = (int*)(aggS + 128); // 32

    int t = threadIdx.x;
    int row = blockIdx.x;
    int b = row >> 8;

    for (int i = t; i < 16384; i += 256) fw2s[i] = fw2[i];
    for (int i = t; i < 3200;  i += 256) fw1s[i] = fw1[i];
    if (t < 128) { fb1s[t] = fb1[t]; fb2s[t] = fb2[t]; }

    int l = t & 31, w = t >> 5;
    int n0 = (l & 7) * 4;             // 8 n-chunks per warp
    int f0 = w*16 + (l >> 3)*4;       // warp-private 16-f block
    float agg4[4] = {};

    const float* fijrow = g_fij + (long long)row*NGg*256;

    for (int tile = 0; tile < 8; tile++) {
        int nbase = tile*32;
        __syncthreads();
        // Fs fill: consecutive-n gmem reads AND smem stores (conflict-free)
        for (int i = t; i < NGg*32; i += 256) {
            int g = i >> 5, n = i & 31;
            Fs[g*36 + n] = fijrow[g*256 + nbase + n];
        }
        if (t < 32) {
            int nn = nbase + t;
            cms[t]  = g_cm[row*256 + nn];                    // slot 255 = 0
            nbrs[t] = (nn < Nn) ? nbr[row*Nn + nn] : 0;
        }
        __syncthreads();

        // stage 1: H[n,f] = ssp(sum_g F[g,n]*fw1[g,f] + b1[f])
        float h[4][4];                 // [fi][ni]
        #pragma unroll
        for (int fi = 0; fi < 4; fi++)
            #pragma unroll
            for (int ni = 0; ni < 4; ni++) h[fi][ni] = fb1s[f0+fi];
        #pragma unroll
        for (int g = 0; g < NGg; g++) {
            float4 fv = *(const float4*)&Fs[g*36 + n0];
            float4 wv = *(const float4*)&fw1s[g*128 + f0];
            float fa[4] = {fv.x, fv.y, fv.z, fv.w};
            float wa[4] = {wv.x, wv.y, wv.z, wv.w};
            #pragma unroll
            for (int fi = 0; fi < 4; fi++)
                #pragma unroll
                for (int ni = 0; ni < 4; ni++) h[fi][ni] += fa[ni]*wa[fi];
        }
        #pragma unroll
        for (int fi = 0; fi < 4; fi++) {
            float4 o;
            o.x = sspf(h[fi][0]); o.y = sspf(h[fi][1]);
            o.z = sspf(h[fi][2]); o.w = sspf(h[fi][3]);
            *(float4*)&Hs[(f0+fi)*36 + n0] = o;
        }
        __syncthreads();

        // stage 2: W'[n,f] = sum_k H[k,n]*fw2[k,f]
        float acc[4][4] = {};          // [fi][ni]
        #pragma unroll 8
        for (int k = 0; k < 128; k++) {
            float4 hv = *(const float4*)&Hs[k*36 + n0];
            float4 wv = *(const float4*)&fw2s[k*128 + f0];
            float ha[4] = {hv.x, hv.y, hv.z, hv.w};
            float wa[4] = {wv.x, wv.y, wv.z, wv.w};
            #pragma unroll
            for (int fi = 0; fi < 4; fi++)
                #pragma unroll
                for (int ni = 0; ni < 4; ni++) acc[fi][ni] += ha[ni]*wa[fi];
        }

        // epilogue: agg += (W' + b2) * cm * y[nbr]
        #pragma unroll
        for (int ni = 0; ni < 4; ni++) {
            float c = cms[n0+ni];
            int j = nbrs[n0+ni];
            float4 yv = *(const float4*)&g_y[(b*Am + j)*NFf + f0];
            float ya[4] = {yv.x, yv.y, yv.z, yv.w};
            #pragma unroll
            for (int fi = 0; fi < 4; fi++)
                agg4[fi] += (acc[fi][ni] + fb2s[f0+fi]) * c * ya[fi];
        }
    }

    __syncthreads();
    if (t < 128) aggS[t] = 0.f;
    __syncthreads();
    #pragma unroll
    for (int fi = 0; fi < 4; fi++) atomicAdd(&aggS[f0+fi], agg4[fi]);
    __syncthreads();
    if (t < 128) g_agg[row*NFf + t] = aggS[t];
}

// ---------------------------------------------------------------------------
// v = ssp(agg @ f2out_w + b1); x += v @ dense_w + b2   (32 atoms per CTA)
__global__ void __launch_bounds__(256) k_out(const float* __restrict__ w1,
        const float* __restrict__ b1v, const float* __restrict__ w2,
        const float* __restrict__ b2v, float* __restrict__ x) {
    extern __shared__ float sm[];
    float* w1s = sm;             // 16384
    float* w2s = w1s + 16384;    // 16384
    float* aT  = w2s + 16384;    // 4608
    float* vT  = aT  + 4608;     // 4608
    float* b1s = vT  + 4608;     // 128
    float* b2s = b1s + 128;      // 128
    int t = threadIdx.x;
    int row0 = blockIdx.x*32;
    for (int i = t; i < 16384; i += 256) { w1s[i] = w1[i]; w2s[i] = w2[i]; }
    if (t < 128) { b1s[t] = b1v[t]; b2s[t] = b2v[t]; }
    for (int i = t; i < 32*128; i += 256) {
        int m = i >> 7, k = i & 127;
        aT[k*36 + m] = g_agg[(row0+m)*NFf + k];
    }
    __syncthreads();
    int fb = t & 31, nb = t >> 5;
    int d0 = fb*4, m0 = nb*4;

    float acc[4][4] = {};
    #pragma unroll 4
    for (int k = 0; k < 128; k++) {
        float4 av = *(const float4*)&aT[k*36 + m0];
        float4 wv = *(const float4*)&w1s[k*128 + d0];
        float aa[4] = {av.x, av.y, av.z, av.w};
        float wa[4] = {wv.x, wv.y, wv.z, wv.w};
        #pragma unroll
        for (int mi = 0; mi < 4; mi++)
            #pragma unroll
            for (int di = 0; di < 4; di++) acc[mi][di] += aa[mi]*wa[di];
    }
    #pragma unroll
    for (int mi = 0; mi < 4; mi++)
        #pragma unroll
        for (int di = 0; di < 4; di++)
            vT[(d0+di)*36 + (m0+mi)] = sspf(acc[mi][di] + b1s[d0+di]);
    __syncthreads();

    float acc2[4][4] = {};
    #pragma unroll 4
    for (int k = 0; k < 128; k++) {
        float4 av = *(const float4*)&vT[k*36 + m0];
        float4 wv = *(const float4*)&w2s[k*128 + d0];
        float aa[4] = {av.x, av.y, av.z, av.w};
        float wa[4] = {wv.x, wv.y, wv.z, wv.w};
        #pragma unroll
        for (int mi = 0; mi < 4; mi++)
            #pragma unroll
            for (int di = 0; di < 4; di++) acc2[mi][di] += aa[mi]*wa[di];
    }
    #pragma unroll
    for (int mi = 0; mi < 4; mi++) {
        float4 xv = *(float4*)&x[(row0+m0+mi)*NBf + d0];
        xv.x += acc2[mi][0] + b2s[d0+0];
        xv.y += acc2[mi][1] + b2s[d0+1];
        xv.z += acc2[mi][2] + b2s[d0+2];
        xv.w += acc2[mi][3] + b2s[d0+3];
        *(float4*)&x[(row0+m0+mi)*NBf + d0] = xv;
    }
}

// ---------------------------------------------------------------------------
extern "C" void kernel_launch(void* const* d_in, const int* in_sizes, int n_in,
                              void* d_out, int out_size) {
    const int*   z    = (const int*)  d_in[0];
    const float* pos  = (const float*)d_in[1];
    const int*   nbr  = (const int*)  d_in[2];
    const float* mask = (const float*)d_in[3];
    const float* emb  = (const float*)d_in[4];
    const float* fw1  = (const float*)d_in[5];
    const float* fb1  = (const float*)d_in[6];
    const float* fw2  = (const float*)d_in[7];
    const float* fb2  = (const float*)d_in[8];
    const float* in2f = (const float*)d_in[9];
    const float* f2w  = (const float*)d_in[10];
    const float* f2b  = (const float*)d_in[11];
    const float* dw   = (const float*)d_in[12];
    const float* db   = (const float*)d_in[13];
    float* x = (float*)d_out;

    const int YSM = (16384 + 4608) * 4;
    const int FSM = (16384 + 3200 + 128 + 128 + 900 + 4608 + 32 + 128 + 32) * 4;
    const int OSM = (16384*2 + 4608*2 + 128*2) * 4;
    cudaFuncSetAttribute(k_y,      cudaFuncAttributeMaxDynamicSharedMemorySize, YSM);
    cudaFuncSetAttribute(k_filter, cudaFuncAttributeMaxDynamicSharedMemorySize, FSM);
    cudaFuncSetAttribute(k_out,    cudaFuncAttributeMaxDynamicSharedMemorySize, OSM);

    k_embed<<<ROWS, 128>>>(z, emb, x);
    k_geo  <<<ROWS, 256>>>(pos, nbr, mask);
    for (int i = 0; i < 3; i++) {
        k_y     <<<ROWS/32, 256, YSM>>>(x, in2f + i*NBf*NFf);
        k_filter<<<ROWS,    256, FSM>>>(nbr, fw1 + i*NGg*NFf, fb1 + i*NFf,
                                        fw2 + i*NFf*NFf, fb2 + i*NFf);
        k_out   <<<ROWS/32, 256, OSM>>>(f2w + i*NFf*NBf, f2b + i*NBf,
                                        dw + i*NBf*NBf, db + i*NBf, x);
    }
}

// round 9
// speedup vs baseline: 4.2053x; 2.4919x over previous
#include <cuda_runtime.h>
#include <cstdint>

// SchNet forward on GB300 — mma.sync m16n8k8.tf32 filter network (R9).
// tcgen05 unavailable (harness targets virtual compute_103, no 'a');
// mma.sync tf32 is base sm_80+ PTX and reaches the tensor pipe as HMMA.
// B=8, A=256, N=255, NB=NF=128, NG=25(pad 32), NI=3.

#define ROWS 2048

__device__ float g_y  [ROWS*128];   // in2f projection
__device__ float g_agg[ROWS*128];   // cfconv aggregate (warp-exclusive writes)

// ---------------------------------------------------------------------------
__device__ __forceinline__ uint32_t f2tf32(float x) {
    uint32_t r; asm("cvt.rna.tf32.f32 %0, %1;" : "=r"(r) : "f"(x)); return r;
}
// D += A(16x8) * B(8x8) tf32, fp32 accum
__device__ __forceinline__ void mma8(float* d, const uint32_t* a, const uint32_t* b) {
    asm volatile("mma.sync.aligned.m16n8k8.row.col.f32.tf32.tf32.f32 "
        "{%0,%1,%2,%3}, {%4,%5,%6,%7}, {%8,%9}, {%0,%1,%2,%3};"
        : "+f"(d[0]), "+f"(d[1]), "+f"(d[2]), "+f"(d[3])
        : "r"(a[0]), "r"(a[1]), "r"(a[2]), "r"(a[3]), "r"(b[0]), "r"(b[1]));
}
// shifted softplus: softplus(x) - ln2  (matches reference ssp)
__device__ __forceinline__ float sspf(float x) {
    float t = -fabsf(x) * 1.4426950408889634f;
    float p; asm("ex2.approx.f32 %0, %1;" : "=f"(p) : "f"(t));
    float q; asm("lg2.approx.f32 %0, %1;" : "=f"(q) : "f"(1.0f + p));
    return fmaxf(x, 0.0f) + (q - 1.0f) * 0.6931471805599453f;
}

// ---------------------------------------------------------------------------
__global__ void k_embed(const int* __restrict__ z, const float* __restrict__ emb,
                        float* __restrict__ x) {
    int row = blockIdx.x, t = threadIdx.x;
    x[row*128 + t] = emb[z[row]*128 + t];
}

// ---------------------------------------------------------------------------
// y = x @ in2f   (32 atoms per CTA, 4x4 register tile, K=128)  [R5, verified]
__global__ void __launch_bounds__(256) k_y(const float* __restrict__ x,
                                           const float* __restrict__ w) {
    extern __shared__ float sm[];
    float* ws = sm;            // 16384
    float* xT = sm + 16384;    // 128*36
    int t = threadIdx.x;
    int row0 = blockIdx.x*32;
    for (int i = t; i < 16384; i += 256) ws[i] = w[i];
    for (int i = t; i < 32*128; i += 256) {
        int m = i >> 7, k = i & 127;
        xT[k*36 + m] = x[(row0+m)*128 + k];
    }
    __syncthreads();
    int fb = t & 31, nb = t >> 5;
    int f0 = fb*4, m0 = nb*4;
    float acc[4][4] = {};
    #pragma unroll 4
    for (int k = 0; k < 128; k++) {
        float4 xv = *(const float4*)&xT[k*36 + m0];
        float4 wv = *(const float4*)&ws[k*128 + f0];
        float xa[4] = {xv.x, xv.y, xv.z, xv.w};
        float wa[4] = {wv.x, wv.y, wv.z, wv.w};
        #pragma unroll
        for (int mi = 0; mi < 4; mi++)
            #pragma unroll
            for (int fi = 0; fi < 4; fi++) acc[mi][fi] += xa[mi]*wa[fi];
    }
    for (int mi = 0; mi < 4; mi++) {
        float4 o = {acc[mi][0], acc[mi][1], acc[mi][2], acc[mi][3]};
        *(float4*)&g_y[(row0+m0+mi)*128 + f0] = o;
    }
}

// ---------------------------------------------------------------------------
// Filter network + cfconv via mma.sync tf32. Grid 296, CTA loops atoms.
// smem (floats): Fs[256][36] | Hs[2][16][132] | Ys[2][16][132] |
//                cms[256] | nbrs[256] | fw1s[32][128]
#define OF_H   9216
#define OF_Y   13440
#define OF_CM  17664
#define OF_NB  17920
#define OF_W1  18176
#define SM_FLT 22272

__global__ void __launch_bounds__(256, 2) k_filter(
        const float* __restrict__ pos, const int* __restrict__ nbrp,
        const float* __restrict__ maskp,
        const float* __restrict__ fw1p, const float* __restrict__ fb1p,
        const float* __restrict__ fw2p, const float* __restrict__ fb2p) {
    extern __shared__ float sm[];
    float* Fs  = sm;
    float* Hs  = sm + OF_H;
    float* Ys  = sm + OF_Y;
    float* cms = sm + OF_CM;
    int*   nbrs= (int*)(sm + OF_NB);
    float* fw1s= sm + OF_W1;

    const int t = threadIdx.x, l = t & 31, w = t >> 5;
    const int g = l >> 2, tg = l & 3;
    const int f0 = w * 16;

    // ---- fw1 -> smem, tf32-converted, zero-padded to k=32 ----
    for (int i = t; i < 32*128; i += 256) {
        int k = i >> 7, f = i & 127;
        fw1s[i] = (k < 25) ? __uint_as_float(f2tf32(fw1p[k*128 + f])) : 0.f;
    }
    // ---- per-CTA register fragments: fw2 B operands + biases ----
    uint32_t fw2f[16][2][2];
    #pragma unroll
    for (int ks = 0; ks < 16; ks++)
        #pragma unroll
        for (int nt = 0; nt < 2; nt++) {
            int col = f0 + nt*8 + g;
            fw2f[ks][nt][0] = f2tf32(fw2p[(ks*8 + tg    )*128 + col]);
            fw2f[ks][nt][1] = f2tf32(fw2p[(ks*8 + tg + 4)*128 + col]);
        }
    float b1f[2][2], b2f[2][2];
    #pragma unroll
    for (int nt = 0; nt < 2; nt++) {
        b1f[nt][0] = fb1p[f0 + nt*8 + tg*2];     b1f[nt][1] = fb1p[f0 + nt*8 + tg*2 + 1];
        b2f[nt][0] = fb2p[f0 + nt*8 + tg*2];     b2f[nt][1] = fb2p[f0 + nt*8 + tg*2 + 1];
    }

    for (int row = blockIdx.x; row < ROWS; row += gridDim.x) {
        int bmol = row >> 8;
        __syncthreads();   // order fw1s fill / prev-atom readers before Fs rewrite
        // ---- fused geometry: slot t of 256 (slot 255 = pad, cm=0) ----
        {
            bool vld = t < 255;
            int   j = vld ? nbrp [row*255 + t] : 0;
            float m = vld ? maskp[row*255 + t] : 0.f;
            const float* pa = pos + row*3;
            const float* pj = pos + (bmol*256 + j)*3;
            float dx = pj[0]-pa[0], dy = pj[1]-pa[1], dz = pj[2]-pa[2];
            float r = sqrtf(dx*dx + dy*dy + dz*dz + 1e-12f) * m;
            float C = (r < 5.0f) ? 0.5f*(cosf(r*0.6283185307179586f) + 1.0f) : 0.f;
            cms[t]  = C * m;
            nbrs[t] = j;
            const float width = 5.0f/24.0f;
            const float coeff = -0.5f/(width*width);
            #pragma unroll
            for (int c = 0; c < 8; c++) {
                uint32_t v[4];
                #pragma unroll
                for (int q = 0; q < 4; q++) {
                    int gg = c*4 + q;
                    float d = r - width*(float)gg;
                    v[q] = (gg < 25) ? f2tf32(__expf(coeff*d*d)) : 0u;
                }
                *(uint4*)&Fs[t*36 + c*4] = make_uint4(v[0], v[1], v[2], v[3]);
            }
        }
        __syncthreads();

        float agg[2][2] = {};
        for (int ch = 0; ch < 16; ch++) {
            float* Hb = Hs + (ch & 1) * 2112;
            float* Yb = Ys + (ch & 1) * 2112;
            // ---- stage 1: H = ssp(F @ fw1 + b1) for warp's 16-f slice ----
            float d0[4] = {b1f[0][0], b1f[0][1], b1f[0][0], b1f[0][1]};
            float d1[4] = {b1f[1][0], b1f[1][1], b1f[1][0], b1f[1][1]};
            int rA = (ch*16 + g) * 36;
            #pragma unroll
            for (int ks = 0; ks < 4; ks++) {
                uint32_t a[4], b0[2], b1r[2];
                a[0] = __float_as_uint(Fs[rA       + ks*8 + tg    ]);
                a[1] = __float_as_uint(Fs[rA + 288 + ks*8 + tg    ]);
                a[2] = __float_as_uint(Fs[rA       + ks*8 + tg + 4]);
                a[3] = __float_as_uint(Fs[rA + 288 + ks*8 + tg + 4]);
                b0[0]  = __float_as_uint(fw1s[(ks*8 + tg    )*128 + f0 + g]);
                b0[1]  = __float_as_uint(fw1s[(ks*8 + tg + 4)*128 + f0 + g]);
                b1r[0] = __float_as_uint(fw1s[(ks*8 + tg    )*128 + f0 + 8 + g]);
                b1r[1] = __float_as_uint(fw1s[(ks*8 + tg + 4)*128 + f0 + 8 + g]);
                mma8(d0, a, b0);
                mma8(d1, a, b1r);
            }
            {   // shifted ssp -> tf32 -> Hb
                uint32_t h00 = f2tf32(sspf(d0[0])), h01 = f2tf32(sspf(d0[1]));
                uint32_t h02 = f2tf32(sspf(d0[2])), h03 = f2tf32(sspf(d0[3]));
                uint32_t h10 = f2tf32(sspf(d1[0])), h11 = f2tf32(sspf(d1[1]));
                uint32_t h12 = f2tf32(sspf(d1[2])), h13 = f2tf32(sspf(d1[3]));
                *(uint2*)&Hb[ g   *132 + f0     + tg*2] = make_uint2(h00, h01);
                *(uint2*)&Hb[(g+8)*132 + f0     + tg*2] = make_uint2(h02, h03);
                *(uint2*)&Hb[ g   *132 + f0 + 8 + tg*2] = make_uint2(h10, h11);
                *(uint2*)&Hb[(g+8)*132 + f0 + 8 + tg*2] = make_uint2(h12, h13);
            }
            // ---- cooperative y-tile stage: rows 2w, 2w+1 of this chunk ----
            {
                int yr = 2*w + (l >> 4), yc = l & 15;
                int jj = nbrs[ch*16 + yr];
                const float4* src = (const float4*)&g_y[(size_t)((bmol << 8) + jj)*128];
                *(float4*)&Yb[yr*132 + yc*4      ] = src[yc];
                *(float4*)&Yb[yr*132 + (yc+16)*4 ] = src[yc+16];
            }
            __syncthreads();
            // ---- stage 2: D2 = H @ fw2 + b2 ----
            float e0[4] = {b2f[0][0], b2f[0][1], b2f[0][0], b2f[0][1]};
            float e1[4] = {b2f[1][0], b2f[1][1], b2f[1][0], b2f[1][1]};
            int rH0 = g*132, rH1 = (g+8)*132;
            #pragma unroll
            for (int ks = 0; ks < 16; ks++) {
                uint32_t a[4];
                a[0] = __float_as_uint(Hb[rH0 + ks*8 + tg    ]);
                a[1] = __float_as_uint(Hb[rH1 + ks*8 + tg    ]);
                a[2] = __float_as_uint(Hb[rH0 + ks*8 + tg + 4]);
                a[3] = __float_as_uint(Hb[rH1 + ks*8 + tg + 4]);
                mma8(e0, a, fw2f[ks][0]);
                mma8(e1, a, fw2f[ks][1]);
            }
            // ---- epilogue: agg += (D2) * cm * y ----
            float cm0 = cms[ch*16 + g], cm1 = cms[ch*16 + g + 8];
            {
                int fc = f0 + tg*2;
                float2 ya = *(float2*)&Yb[rH0 + fc];
                float2 yb = *(float2*)&Yb[rH1 + fc];
                agg[0][0] += e0[0]*cm0*ya.x + e0[2]*cm1*yb.x;
                agg[0][1] += e0[1]*cm0*ya.y + e0[3]*cm1*yb.y;
                float2 yc2 = *(float2*)&Yb[rH0 + fc + 8];
                float2 yd  = *(float2*)&Yb[rH1 + fc + 8];
                agg[1][0] += e1[0]*cm0*yc2.x + e1[2]*cm1*yd.x;
                agg[1][1] += e1[1]*cm0*yc2.y + e1[3]*cm1*yd.y;
            }
        }
        // ---- reduce over n-lanes (g bits 2..4) and write warp-exclusive slice ----
        #pragma unroll
        for (int mk = 4; mk <= 16; mk <<= 1) {
            #pragma unroll
            for (int nt = 0; nt < 2; nt++) {
                agg[nt][0] += __shfl_xor_sync(0xffffffffu, agg[nt][0], mk);
                agg[nt][1] += __shfl_xor_sync(0xffffffffu, agg[nt][1], mk);
            }
        }
        if (l < 4) {
            *(float2*)&g_agg[(size_t)row*128 + f0     + l*2] = make_float2(agg[0][0], agg[0][1]);
            *(float2*)&g_agg[(size_t)row*128 + f0 + 8 + l*2] = make_float2(agg[1][0], agg[1][1]);
        }
    }
}

// ---------------------------------------------------------------------------
// v = ssp(agg @ f2out_w + b1); x += v @ dense_w + b2   [R5, verified]
__global__ void __launch_bounds__(256) k_out(const float* __restrict__ w1,
        const float* __restrict__ b1v, const float* __restrict__ w2,
        const float* __restrict__ b2v, float* __restrict__ x) {
    extern __shared__ float sm[];
    float* w1s = sm;             // 16384
    float* w2s = w1s + 16384;    // 16384
    float* aT  = w2s + 16384;    // 4608
    float* vT  = aT  + 4608;     // 4608
    float* b1s = vT  + 4608;     // 128
    float* b2s = b1s + 128;      // 128
    int t = threadIdx.x;
    int row0 = blockIdx.x*32;
    for (int i = t; i < 16384; i += 256) { w1s[i] = w1[i]; w2s[i] = w2[i]; }
    if (t < 128) { b1s[t] = b1v[t]; b2s[t] = b2v[t]; }
    for (int i = t; i < 32*128; i += 256) {
        int m = i >> 7, k = i & 127;
        aT[k*36 + m] = g_agg[(size_t)(row0+m)*128 + k];
    }
    __syncthreads();
    int fb = t & 31, nb = t >> 5;
    int d0 = fb*4, m0 = nb*4;

    float acc[4][4] = {};
    #pragma unroll 4
    for (int k = 0; k < 128; k++) {
        float4 av = *(const float4*)&aT[k*36 + m0];
        float4 wv = *(const float4*)&w1s[k*128 + d0];
        float aa[4] = {av.x, av.y, av.z, av.w};
        float wa[4] = {wv.x, wv.y, wv.z, wv.w};
        #pragma unroll
        for (int mi = 0; mi < 4; mi++)
            #pragma unroll
            for (int di = 0; di < 4; di++) acc[mi][di] += aa[mi]*wa[di];
    }
    #pragma unroll
    for (int mi = 0; mi < 4; mi++)
        #pragma unroll
        for (int di = 0; di < 4; di++)
            vT[(d0+di)*36 + (m0+mi)] = sspf(acc[mi][di] + b1s[d0+di]);
    __syncthreads();

    float acc2[4][4] = {};
    #pragma unroll 4
    for (int k = 0; k < 128; k++) {
        float4 av = *(const float4*)&vT[k*36 + m0];
        float4 wv = *(const float4*)&w2s[k*128 + d0];
        float aa[4] = {av.x, av.y, av.z, av.w};
        float wa[4] = {wv.x, wv.y, wv.z, wv.w};
        #pragma unroll
        for (int mi = 0; mi < 4; mi++)
            #pragma unroll
            for (int di = 0; di < 4; di++) acc2[mi][di] += aa[mi]*wa[di];
    }
    #pragma unroll
    for (int mi = 0; mi < 4; mi++) {
        float4 xv = *(float4*)&x[(row0+m0+mi)*128 + d0];
        xv.x += acc2[mi][0] + b2s[d0+0];
        xv.y += acc2[mi][1] + b2s[d0+1];
        xv.z += acc2[mi][2] + b2s[d0+2];
        xv.w += acc2[mi][3] + b2s[d0+3];
        *(float4*)&x[(row0+m0+mi)*128 + d0] = xv;
    }
}

// ---------------------------------------------------------------------------
extern "C" void kernel_launch(void* const* d_in, const int* in_sizes, int n_in,
                              void* d_out, int out_size) {
    const int*   z    = (const int*)  d_in[0];
    const float* pos  = (const float*)d_in[1];
    const int*   nbr  = (const int*)  d_in[2];
    const float* mask = (const float*)d_in[3];
    const float* emb  = (const float*)d_in[4];
    const float* fw1  = (const float*)d_in[5];
    const float* fb1  = (const float*)d_in[6];
    const float* fw2  = (const float*)d_in[7];
    const float* fb2  = (const float*)d_in[8];
    const float* in2f = (const float*)d_in[9];
    const float* f2w  = (const float*)d_in[10];
    const float* f2b  = (const float*)d_in[11];
    const float* dw   = (const float*)d_in[12];
    const float* db   = (const float*)d_in[13];
    float* x = (float*)d_out;

    const int YSM = (16384 + 4608) * 4;
    const int FSM = SM_FLT * 4;                 // 89,088 B -> 2 CTAs/SM
    const int OSM = (16384*2 + 4608*2 + 128*2) * 4;
    cudaFuncSetAttribute(k_y,      cudaFuncAttributeMaxDynamicSharedMemorySize, YSM);
    cudaFuncSetAttribute(k_filter, cudaFuncAttributeMaxDynamicSharedMemorySize, FSM);
    cudaFuncSetAttribute(k_out,    cudaFuncAttributeMaxDynamicSharedMemorySize, OSM);

    k_embed<<<ROWS, 128>>>(z, emb, x);
    for (int i = 0; i < 3; i++) {
        k_y     <<<ROWS/32, 256, YSM>>>(x, in2f + i*128*128);
        k_filter<<<296, 256, FSM>>>(pos, nbr, mask,
                                    fw1 + i*25*128, fb1 + i*128,
                                    fw2 + i*128*128, fb2 + i*128);
        k_out   <<<ROWS/32, 256, OSM>>>(f2w + i*128*128, f2b + i*128,
                                        dw + i*128*128, db + i*128, x);
    }
}

// round 15
// speedup vs baseline: 6.9815x; 1.6602x over previous
#include <cuda_runtime.h>
#include <cstdint>

// SchNet forward on GB300 — bf16 mma.sync m16n8k16 filter network (R10..R15).
// B=8, A=256, N=255, NB=NF=128, NG=25(pad 32), NI=3.

#define ROWS 2048

__device__ float g_y  [ROWS*128];   // in2f projection
__device__ float g_agg[ROWS*128];   // cfconv aggregate
__device__ float g_v  [ROWS*128];   // intermediate v (between out1/out2)

// ---------------------------------------------------------------------------
__device__ __forceinline__ uint32_t pk(float lo, float hi) {
    uint32_t r; asm("cvt.rn.bf16x2.f32 %0, %2, %1;" : "=r"(r) : "f"(lo), "f"(hi));
    return r;   // low half = lo (even k), high half = hi (odd k)
}
// D += A(16x16) * B(16x8) bf16, fp32 accum
__device__ __forceinline__ void mma16(float* d, const uint32_t* a, const uint32_t* b) {
    asm volatile("mma.sync.aligned.m16n8k16.row.col.f32.bf16.bf16.f32 "
        "{%0,%1,%2,%3}, {%4,%5,%6,%7}, {%8,%9}, {%0,%1,%2,%3};"
        : "+f"(d[0]), "+f"(d[1]), "+f"(d[2]), "+f"(d[3])
        : "r"(a[0]), "r"(a[1]), "r"(a[2]), "r"(a[3]), "r"(b[0]), "r"(b[1]));
}
// shifted softplus: softplus(x) - ln2
__device__ __forceinline__ float sspf(float x) {
    float t = -fabsf(x) * 1.4426950408889634f;
    float p; asm("ex2.approx.f32 %0, %1;" : "=f"(p) : "f"(t));
    float q; asm("lg2.approx.f32 %0, %1;" : "=f"(q) : "f"(1.0f + p));
    return fmaxf(x, 0.0f) + (q - 1.0f) * 0.6931471805599453f;
}

// ---------------------------------------------------------------------------
__global__ void k_embed(const int* __restrict__ z, const float* __restrict__ emb,
                        float* __restrict__ x) {
    int row = blockIdx.x, t = threadIdx.x;
    x[row*128 + t] = emb[z[row]*128 + t];
}

// ---------------------------------------------------------------------------
// Small dense helpers: 256 CTAs x 8 atoms, weights in smem, broadcast A.
__global__ void __launch_bounds__(256) k_y(const float* __restrict__ x,
                                           const float* __restrict__ w) {
    extern __shared__ float sm[];
    float* ws = sm;            // 16384
    float* xT = sm + 16384;    // 128*9
    int t = threadIdx.x;
    int row0 = blockIdx.x*8;
    for (int i = t; i < 16384; i += 256) ws[i] = w[i];
    for (int i = t; i < 8*128; i += 256) {
        int m = i >> 7, k = i & 127;
        xT[k*9 + m] = x[(row0+m)*128 + k];
    }
    __syncthreads();
    int na = t >> 5, f0 = (t & 31)*4;
    float acc[4] = {};
    #pragma unroll 4
    for (int k = 0; k < 128; k++) {
        float av = xT[k*9 + na];
        float4 wv = *(const float4*)&ws[k*128 + f0];
        acc[0] += av*wv.x; acc[1] += av*wv.y; acc[2] += av*wv.z; acc[3] += av*wv.w;
    }
    *(float4*)&g_y[(size_t)(row0+na)*128 + f0] = make_float4(acc[0],acc[1],acc[2],acc[3]);
}

__global__ void __launch_bounds__(256) k_out1(const float* __restrict__ w,
                                              const float* __restrict__ bv) {
    extern __shared__ float sm[];
    float* ws = sm;            // 16384
    float* aT = sm + 16384;    // 128*9
    float* bs = aT + 1152;     // 128
    int t = threadIdx.x;
    int row0 = blockIdx.x*8;
    for (int i = t; i < 16384; i += 256) ws[i] = w[i];
    if (t < 128) bs[t] = bv[t];
    for (int i = t; i < 8*128; i += 256) {
        int m = i >> 7, k = i & 127;
        aT[k*9 + m] = g_agg[(size_t)(row0+m)*128 + k];
    }
    __syncthreads();
    int na = t >> 5, f0 = (t & 31)*4;
    float acc[4] = {};
    #pragma unroll 4
    for (int k = 0; k < 128; k++) {
        float av = aT[k*9 + na];
        float4 wv = *(const float4*)&ws[k*128 + f0];
        acc[0] += av*wv.x; acc[1] += av*wv.y; acc[2] += av*wv.z; acc[3] += av*wv.w;
    }
    float4 o;
    o.x = sspf(acc[0] + bs[f0+0]); o.y = sspf(acc[1] + bs[f0+1]);
    o.z = sspf(acc[2] + bs[f0+2]); o.w = sspf(acc[3] + bs[f0+3]);
    *(float4*)&g_v[(size_t)(row0+na)*128 + f0] = o;
}

__global__ void __launch_bounds__(256) k_out2(const float* __restrict__ w,
                                              const float* __restrict__ bv,
                                              float* __restrict__ x) {
    extern __shared__ float sm[];
    float* ws = sm;            // 16384
    float* aT = sm + 16384;    // 128*9
    float* bs = aT + 1152;     // 128
    int t = threadIdx.x;
    int row0 = blockIdx.x*8;
    for (int i = t; i < 16384; i += 256) ws[i] = w[i];
    if (t < 128) bs[t] = bv[t];
    for (int i = t; i < 8*128; i += 256) {
        int m = i >> 7, k = i & 127;
        aT[k*9 + m] = g_v[(size_t)(row0+m)*128 + k];
    }
    __syncthreads();
    int na = t >> 5, f0 = (t & 31)*4;
    float acc[4] = {};
    #pragma unroll 4
    for (int k = 0; k < 128; k++) {
        float av = aT[k*9 + na];
        float4 wv = *(const float4*)&ws[k*128 + f0];
        acc[0] += av*wv.x; acc[1] += av*wv.y; acc[2] += av*wv.z; acc[3] += av*wv.w;
    }
    float4 xv = *(float4*)&x[(size_t)(row0+na)*128 + f0];
    xv.x += acc[0] + bs[f0+0]; xv.y += acc[1] + bs[f0+1];
    xv.z += acc[2] + bs[f0+2]; xv.w += acc[3] + bs[f0+3];
    *(float4*)&x[(size_t)(row0+na)*128 + f0] = xv;
}

// ---------------------------------------------------------------------------
// Filter network + cfconv via bf16 mma.sync. Grid 296, CTA loops atoms.
// smem (u32): Fs[256][20] | Hs[2][16][68] | Ys[2][16][132] |
//             cms[256] | nbrs[256] | fw1pk[16][136]
#define OF_H   5120
#define OF_Y   7296
#define OF_CM  11520
#define OF_NB  11776
#define OF_W1  12032
#define SM_U   14208

__global__ void __launch_bounds__(256, 2) k_filter(
        const float* __restrict__ pos, const int* __restrict__ nbrp,
        const float* __restrict__ maskp,
        const float* __restrict__ fw1p, const float* __restrict__ fb1p,
        const float* __restrict__ fw2p, const float* __restrict__ fb2p) {
    extern __shared__ uint32_t smu[];
    uint32_t* FsU = smu;
    uint32_t* HsU = smu + OF_H;
    float*    Ys  = (float*)(smu + OF_Y);
    float*    cms = (float*)(smu + OF_CM);
    int*      nbrs= (int*)  (smu + OF_NB);
    uint32_t* W1  = smu + OF_W1;

    const int t = threadIdx.x, l = t & 31, w = t >> 5;
    const int g = l >> 2, tg = l & 3;
    const int f0 = w * 16;

    // ---- fw1 packed bf16 pairs -> smem (stride 136 u32: conflict-free B reads) ----
    for (int i = t; i < 16*128; i += 256) {
        int kp = i >> 7, f = i & 127;
        float lo = (2*kp     < 25) ? fw1p[(2*kp    )*128 + f] : 0.f;
        float hi = (2*kp + 1 < 25) ? fw1p[(2*kp + 1)*128 + f] : 0.f;
        W1[kp*136 + f] = pk(lo, hi);
    }
    // ---- fw2 B fragments -> registers (bf16 pairs) ----
    uint32_t fw2f[8][2][2];
    #pragma unroll
    for (int ks = 0; ks < 8; ks++)
        #pragma unroll
        for (int nt = 0; nt < 2; nt++) {
            int col = f0 + nt*8 + g;
            int k0 = ks*16 + tg*2;
            fw2f[ks][nt][0] = pk(fw2p[(k0    )*128 + col], fw2p[(k0+1)*128 + col]);
            fw2f[ks][nt][1] = pk(fw2p[(k0+8)*128 + col], fw2p[(k0+9)*128 + col]);
        }
    float b1f[2][2], b2f[2][2];
    #pragma unroll
    for (int nt = 0; nt < 2; nt++) {
        b1f[nt][0] = fb1p[f0 + nt*8 + tg*2];  b1f[nt][1] = fb1p[f0 + nt*8 + tg*2 + 1];
        b2f[nt][0] = fb2p[f0 + nt*8 + tg*2];  b2f[nt][1] = fb2p[f0 + nt*8 + tg*2 + 1];
    }

    for (int row = blockIdx.x; row < ROWS; row += gridDim.x) {
        int bmol = row >> 8;
        __syncthreads();   // protect Fs/cms/nbrs/H/Y from previous atom's readers
        // ---- fused geometry: slot t of 256 (slot 255 = pad, cm=0) ----
        {
            bool vld = t < 255;
            int   j = vld ? nbrp [row*255 + t] : 0;
            float m = vld ? maskp[row*255 + t] : 0.f;
            const float* pa = pos + row*3;
            const float* pj = pos + (bmol*256 + j)*3;
            float dx = pj[0]-pa[0], dy = pj[1]-pa[1], dz = pj[2]-pa[2];
            float r = sqrtf(dx*dx + dy*dy + dz*dz + 1e-12f) * m;
            float C = (r < 5.0f) ? 0.5f*(cosf(r*0.6283185307179586f) + 1.0f) : 0.f;
            cms[t]  = C * m;
            nbrs[t] = j;
            const float width = 5.0f/24.0f;
            const float coeff = -0.5f/(width*width);
            float fv[32];
            #pragma unroll
            for (int gg = 0; gg < 32; gg++) {
                float d = r - width*(float)gg;
                fv[gg] = (gg < 25) ? __expf(coeff*d*d) : 0.f;
            }
            #pragma unroll
            for (int c = 0; c < 4; c++) {
                uint4 v;
                v.x = pk(fv[8*c+0], fv[8*c+1]);
                v.y = pk(fv[8*c+2], fv[8*c+3]);
                v.z = pk(fv[8*c+4], fv[8*c+5]);
                v.w = pk(fv[8*c+6], fv[8*c+7]);
                *(uint4*)&FsU[t*20 + c*4] = v;
            }
        }
        __syncthreads();

        float agg[2][2] = {};
        for (int ch = 0; ch < 16; ch++) {
            uint32_t* Hb = HsU + (ch & 1) * 1088;
            float*    Yb = Ys  + (ch & 1) * 2112;
            // ---- stage 1: H = ssp(F @ fw1 + b1), warp's 16-f slice ----
            float d0[4] = {b1f[0][0], b1f[0][1], b1f[0][0], b1f[0][1]};
            float d1[4] = {b1f[1][0], b1f[1][1], b1f[1][0], b1f[1][1]};
            int rA = (ch*16 + g) * 20;
            #pragma unroll
            for (int ks = 0; ks < 2; ks++) {
                uint32_t a[4], bb[2];
                a[0] = FsU[rA       + ks*8 + tg];
                a[1] = FsU[rA + 160 + ks*8 + tg];
                a[2] = FsU[rA       + ks*8 + tg + 4];
                a[3] = FsU[rA + 160 + ks*8 + tg + 4];
                int kp = ks*8 + tg;
                bb[0] = W1[ kp     *136 + f0 + g];
                bb[1] = W1[(kp + 4)*136 + f0 + g];
                mma16(d0, a, bb);
                bb[0] = W1[ kp     *136 + f0 + 8 + g];
                bb[1] = W1[(kp + 4)*136 + f0 + 8 + g];
                mma16(d1, a, bb);
            }
            int hc = (f0 >> 1) + tg;
            Hb[ g   *68 + hc    ] = pk(sspf(d0[0]), sspf(d0[1]));
            Hb[(g+8)*68 + hc    ] = pk(sspf(d0[2]), sspf(d0[3]));
            Hb[ g   *68 + hc + 4] = pk(sspf(d1[0]), sspf(d1[1]));
            Hb[(g+8)*68 + hc + 4] = pk(sspf(d1[2]), sspf(d1[3]));
            // ---- cooperative y-tile: rows 2w, 2w+1 of this chunk ----
            {
                int yr = 2*w + (l >> 4), yc = l & 15;
                int jj = nbrs[ch*16 + yr];
                const float4* src = (const float4*)&g_y[(size_t)((bmol << 8) + jj)*128];
                *(float4*)&Yb[yr*132 + yc*4      ] = src[yc];
                *(float4*)&Yb[yr*132 + (yc+16)*4 ] = src[yc+16];
            }
            __syncthreads();
            // ---- stage 2: D2 = H @ fw2 + b2 ----
            float e0[4] = {b2f[0][0], b2f[0][1], b2f[0][0], b2f[0][1]};
            float e1[4] = {b2f[1][0], b2f[1][1], b2f[1][0], b2f[1][1]};
            int rH0 = g*68, rH1 = (g+8)*68;
            #pragma unroll
            for (int ks = 0; ks < 8; ks++) {
                uint32_t a[4];
                a[0] = Hb[rH0 + ks*8 + tg];
                a[1] = Hb[rH1 + ks*8 + tg];
                a[2] = Hb[rH0 + ks*8 + tg + 4];
                a[3] = Hb[rH1 + ks*8 + tg + 4];
                mma16(e0, a, fw2f[ks][0]);
                mma16(e1, a, fw2f[ks][1]);
            }
            // ---- epilogue: agg += D2 * cm * y ----
            float cm0 = cms[ch*16 + g], cm1 = cms[ch*16 + g + 8];
            {
                int rY0 = g*132, rY1 = (g+8)*132;
                int fc = f0 + tg*2;
                float2 ya = *(float2*)&Yb[rY0 + fc];
                float2 yb = *(float2*)&Yb[rY1 + fc];
                agg[0][0] += e0[0]*cm0*ya.x + e0[2]*cm1*yb.x;
                agg[0][1] += e0[1]*cm0*ya.y + e0[3]*cm1*yb.y;
                float2 yc2 = *(float2*)&Yb[rY0 + fc + 8];
                float2 yd  = *(float2*)&Yb[rY1 + fc + 8];
                agg[1][0] += e1[0]*cm0*yc2.x + e1[2]*cm1*yd.x;
                agg[1][1] += e1[1]*cm0*yc2.y + e1[3]*cm1*yd.y;
            }
        }
        // ---- reduce over n-lanes and write warp-exclusive slice ----
        #pragma unroll
        for (int mk = 4; mk <= 16; mk <<= 1) {
            #pragma unroll
            for (int nt = 0; nt < 2; nt++) {
                agg[nt][0] += __shfl_xor_sync(0xffffffffu, agg[nt][0], mk);
                agg[nt][1] += __shfl_xor_sync(0xffffffffu, agg[nt][1], mk);
            }
        }
        if (l < 4) {
            *(float2*)&g_agg[(size_t)row*128 + f0     + l*2] = make_float2(agg[0][0], agg[0][1]);
            *(float2*)&g_agg[(size_t)row*128 + f0 + 8 + l*2] = make_float2(agg[1][0], agg[1][1]);
        }
    }
}

// ---------------------------------------------------------------------------
extern "C" void kernel_launch(void* const* d_in, const int* in_sizes, int n_in,
                              void* d_out, int out_size) {
    const int*   z    = (const int*)  d_in[0];
    const float* pos  = (const float*)d_in[1];
    const int*   nbr  = (const int*)  d_in[2];
    const float* mask = (const float*)d_in[3];
    const float* emb  = (const float*)d_in[4];
    const float* fw1  = (const float*)d_in[5];
    const float* fb1  = (const float*)d_in[6];
    const float* fw2  = (const float*)d_in[7];
    const float* fb2  = (const float*)d_in[8];
    const float* in2f = (const float*)d_in[9];
    const float* f2w  = (const float*)d_in[10];
    const float* f2b  = (const float*)d_in[11];
    const float* dw   = (const float*)d_in[12];
    const float* db   = (const float*)d_in[13];
    float* x = (float*)d_out;

    const int YSM = (16384 + 1152) * 4;
    const int LSM = (16384 + 1152 + 128) * 4;
    const int FSM = SM_U * 4;                  // 56,832 B -> 2 CTAs/SM
    cudaFuncSetAttribute(k_y,      cudaFuncAttributeMaxDynamicSharedMemorySize, YSM);
    cudaFuncSetAttribute(k_out1,   cudaFuncAttributeMaxDynamicSharedMemorySize, LSM);
    cudaFuncSetAttribute(k_out2,   cudaFuncAttributeMaxDynamicSharedMemorySize, LSM);
    cudaFuncSetAttribute(k_filter, cudaFuncAttributeMaxDynamicSharedMemorySize, FSM);

    k_embed<<<ROWS, 128>>>(z, emb, x);
    for (int i = 0; i < 3; i++) {
        k_y     <<<ROWS/8, 256, YSM>>>(x, in2f + i*128*128);
        k_filter<<<296, 256, FSM>>>(pos, nbr, mask,
                                    fw1 + i*25*128, fb1 + i*128,
                                    fw2 + i*128*128, fb2 + i*128);
        k_out1  <<<ROWS/8, 256, LSM>>>(f2w + i*128*128, f2b + i*128);
        k_out2  <<<ROWS/8, 256, LSM>>>(dw + i*128*128, db + i*128, x);
    }
}